// round 1
// baseline (speedup 1.0000x reference)
#include <cuda_runtime.h>

#define BB 2
#define HH 32
#define SS 16384
#define DD 64
#define NHEADS (BB*HH)
#define SPLIT 32
#define CHUNK (SS/SPLIT)   /* 512 */
#define TS 32
#define BS 64              /* s-rows per phase2 block */

/* scratch: deterministic partials + reduced memory/norm (no runtime alloc) */
__device__ float g_part[(size_t)NHEADS * SPLIT * 4160];
__device__ float g_mem [(size_t)NHEADS * 4096];
__device__ float g_norm[(size_t)NHEADS * 64];

__device__ __forceinline__ float elu1(float x) {
    return x > 0.0f ? x + 1.0f : __expf(x);
}

/* ---------------- Phase 1: per-chunk partial memory + norm ---------------- */
__global__ void __launch_bounds__(256) phase1(const float* __restrict__ kk,
                                              const float* __restrict__ vv) {
    __shared__ float sk[TS][64];
    __shared__ float sv[TS][64];

    const int bx    = blockIdx.x;
    const int head  = bx / SPLIT;
    const int chunk = bx % SPLIT;
    const int tid   = threadIdx.x;
    const int dk0   = (tid >> 4) * 4;   /* 0..60 */
    const int dv0   = (tid & 15) * 4;   /* 0..60 */

    float acc[4][4] = {};
    float nrm[4]    = {0.f, 0.f, 0.f, 0.f};

    const float* kbase = kk + ((size_t)head * SS + (size_t)chunk * CHUNK) * DD;
    const float* vbase = vv + ((size_t)head * SS + (size_t)chunk * CHUNK) * DD;

    for (int it = 0; it < CHUNK / TS; ++it) {
        __syncthreads();
        /* cooperative load of 32 rows of K (feature-mapped) and V */
        #pragma unroll
        for (int p = 0; p < 2; ++p) {
            int f = tid + p * 256;           /* float4 index 0..511 */
            int r = f >> 4;
            int c = (f & 15) * 4;
            float4 kf = *(const float4*)(kbase + (size_t)(it * TS + r) * DD + c);
            kf.x = elu1(kf.x); kf.y = elu1(kf.y); kf.z = elu1(kf.z); kf.w = elu1(kf.w);
            *(float4*)&sk[r][c] = kf;
            *(float4*)&sv[r][c] = *(const float4*)(vbase + (size_t)(it * TS + r) * DD + c);
        }
        __syncthreads();

        #pragma unroll 4
        for (int s = 0; s < TS; ++s) {
            float4 kf4 = *(float4*)&sk[s][dk0];
            float4 vv4 = *(float4*)&sv[s][dv0];
            float kfv[4] = {kf4.x, kf4.y, kf4.z, kf4.w};
            float vvv[4] = {vv4.x, vv4.y, vv4.z, vv4.w};
            #pragma unroll
            for (int i = 0; i < 4; ++i)
                #pragma unroll
                for (int j = 0; j < 4; ++j)
                    acc[i][j] += kfv[i] * vvv[j];
            if (dv0 == 0) {
                #pragma unroll
                for (int i = 0; i < 4; ++i) nrm[i] += kfv[i];
            }
        }
    }

    /* deterministic partial write (every element of the 4160 slot is covered) */
    float* outp = g_part + (size_t)bx * 4160;
    #pragma unroll
    for (int i = 0; i < 4; ++i) {
        *(float4*)&outp[(dk0 + i) * 64 + dv0] =
            make_float4(acc[i][0], acc[i][1], acc[i][2], acc[i][3]);
    }
    if (dv0 == 0) {
        *(float4*)&outp[4096 + dk0] = make_float4(nrm[0], nrm[1], nrm[2], nrm[3]);
    }
}

/* ---------------- Reduce: sum 32 partials per head ---------------- */
__global__ void __launch_bounds__(256) reduce_k() {
    const int head = blockIdx.x;
    for (int e = threadIdx.x; e < 4160; e += 256) {
        float s = 0.f;
        #pragma unroll 4
        for (int c = 0; c < SPLIT; ++c)
            s += g_part[((size_t)head * SPLIT + c) * 4160 + e];
        if (e < 4096) g_mem[(size_t)head * 4096 + e] = s;
        else          g_norm[(size_t)head * 64 + (e - 4096)] = s;
    }
}

/* ---------------- Phase 2: retrieval GEMM + normalization ---------------- */
__global__ void __launch_bounds__(256) phase2(const float* __restrict__ q,
                                              float* __restrict__ outg) {
    /* rows padded to 68 floats to avoid bank conflicts on column-strided reads */
    __shared__ float sM[64 * 68];
    __shared__ float sQ[64 * 68];
    __shared__ float snorm[64];
    __shared__ float sdenom[64];

    const int bx   = blockIdx.x;
    const int head = bx >> 8;        /* SS/BS = 256 blocks per head */
    const int sb   = bx & 255;
    const int tid  = threadIdx.x;

    const float* mbase = g_mem + (size_t)head * 4096;
    const float* qbase = q + ((size_t)head * SS + (size_t)sb * BS) * DD;

    #pragma unroll
    for (int p = 0; p < 4; ++p) {
        int f = tid + p * 256;       /* float4 index 0..1023 */
        int r = f >> 4;
        int c = (f & 15) * 4;
        *(float4*)&sM[r * 68 + c] = *(const float4*)(mbase + (size_t)r * 64 + c);
        float4 qq = *(const float4*)(qbase + (size_t)r * 64 + c);
        qq.x = elu1(qq.x); qq.y = elu1(qq.y); qq.z = elu1(qq.z); qq.w = elu1(qq.w);
        *(float4*)&sQ[r * 68 + c] = qq;
    }
    if (tid < 64) snorm[tid] = g_norm[(size_t)head * 64 + tid];
    __syncthreads();

    if (tid < 64) {
        float s = 0.f;
        #pragma unroll 8
        for (int dk = 0; dk < 64; ++dk) s += sQ[tid * 68 + dk] * snorm[dk];
        sdenom[tid] = s;
    }
    __syncthreads();

    const int st  = tid >> 4;
    const int dt  = tid & 15;
    const int s0  = st * 4;
    const int dv0 = dt * 4;

    float acc[4][4] = {};

    #pragma unroll 4
    for (int dk0 = 0; dk0 < 64; dk0 += 4) {
        float4 m[4];
        #pragma unroll
        for (int j = 0; j < 4; ++j)
            m[j] = *(float4*)&sM[(dk0 + j) * 68 + dv0];
        #pragma unroll
        for (int i = 0; i < 4; ++i) {
            float4 qv = *(float4*)&sQ[(s0 + i) * 68 + dk0];
            acc[i][0] += qv.x * m[0].x + qv.y * m[1].x + qv.z * m[2].x + qv.w * m[3].x;
            acc[i][1] += qv.x * m[0].y + qv.y * m[1].y + qv.z * m[2].y + qv.w * m[3].y;
            acc[i][2] += qv.x * m[0].z + qv.y * m[1].z + qv.z * m[2].z + qv.w * m[3].z;
            acc[i][3] += qv.x * m[0].w + qv.y * m[1].w + qv.z * m[2].w + qv.w * m[3].w;
        }
    }

    float* obase = outg + ((size_t)head * SS + (size_t)sb * BS) * DD;
    #pragma unroll
    for (int i = 0; i < 4; ++i) {
        float inv = 1.0f / sdenom[s0 + i];
        *(float4*)&obase[(size_t)(s0 + i) * 64 + dv0] =
            make_float4(acc[i][0] * inv, acc[i][1] * inv,
                        acc[i][2] * inv, acc[i][3] * inv);
    }
}

extern "C" void kernel_launch(void* const* d_in, const int* in_sizes, int n_in,
                              void* d_out, int out_size) {
    const float* q = (const float*)d_in[0];
    const float* k = (const float*)d_in[1];
    const float* v = (const float*)d_in[2];
    float* out = (float*)d_out;

    phase1<<<NHEADS * SPLIT, 256>>>(k, v);
    reduce_k<<<NHEADS, 256>>>();
    phase2<<<NHEADS * (SS / BS), 256>>>(q, out);
}

// round 2
// speedup vs baseline: 1.1522x; 1.1522x over previous
#include <cuda_runtime.h>

#define BB 2
#define HH 32
#define SS 16384
#define DD 64
#define NHEADS (BB*HH)
#define SPLIT 64
#define CHUNK (SS/SPLIT)   /* 256 */
#define TS 32
#define BS 64              /* s-rows per phase2 block */

/* scratch: deterministic partials + reduced memory/norm (no runtime alloc) */
__device__ float g_part[(size_t)NHEADS * SPLIT * 4160];
__device__ float g_mem [(size_t)NHEADS * 4096];
__device__ float g_norm[(size_t)NHEADS * 64];

__device__ __forceinline__ float elu1(float x) {
    return x > 0.0f ? x + 1.0f : __expf(x);
}

/* ------------- Phase 1: per-chunk partial memory + norm (8x4 tile) ------------- */
__global__ void __launch_bounds__(128) phase1(const float* __restrict__ kk,
                                              const float* __restrict__ vv) {
    __shared__ float sk[TS][64];
    __shared__ float sv[TS][64];

    const int bx    = blockIdx.x;
    const int head  = bx / SPLIT;
    const int chunk = bx % SPLIT;
    const int tid   = threadIdx.x;
    const int dk0   = (tid >> 4) * 8;   /* 0..56 */
    const int dv0   = (tid & 15) * 4;   /* 0..60 */

    float acc[8][4] = {};
    float nrm[8]    = {};

    const float* kbase = kk + ((size_t)head * SS + (size_t)chunk * CHUNK) * DD;
    const float* vbase = vv + ((size_t)head * SS + (size_t)chunk * CHUNK) * DD;

    for (int it = 0; it < CHUNK / TS; ++it) {
        __syncthreads();
        /* cooperative load of 32 rows of K (feature-mapped) and V */
        #pragma unroll
        for (int p = 0; p < 4; ++p) {
            int f = tid + p * 128;           /* float4 index 0..511 */
            int r = f >> 4;
            int c = (f & 15) * 4;
            float4 kf = *(const float4*)(kbase + (size_t)(it * TS + r) * DD + c);
            kf.x = elu1(kf.x); kf.y = elu1(kf.y); kf.z = elu1(kf.z); kf.w = elu1(kf.w);
            *(float4*)&sk[r][c] = kf;
            *(float4*)&sv[r][c] = *(const float4*)(vbase + (size_t)(it * TS + r) * DD + c);
        }
        __syncthreads();

        #pragma unroll 4
        for (int s = 0; s < TS; ++s) {
            float4 ka = *(float4*)&sk[s][dk0];
            float4 kb = *(float4*)&sk[s][dk0 + 4];
            float4 vv4 = *(float4*)&sv[s][dv0];
            float kfv[8] = {ka.x, ka.y, ka.z, ka.w, kb.x, kb.y, kb.z, kb.w};
            float vvv[4] = {vv4.x, vv4.y, vv4.z, vv4.w};
            #pragma unroll
            for (int i = 0; i < 8; ++i) {
                #pragma unroll
                for (int j = 0; j < 4; ++j)
                    acc[i][j] += kfv[i] * vvv[j];
            }
            if (dv0 == 0) {
                #pragma unroll
                for (int i = 0; i < 8; ++i) nrm[i] += kfv[i];
            }
        }
    }

    /* deterministic partial write */
    float* outp = g_part + (size_t)bx * 4160;
    #pragma unroll
    for (int i = 0; i < 8; ++i) {
        *(float4*)&outp[(dk0 + i) * 64 + dv0] =
            make_float4(acc[i][0], acc[i][1], acc[i][2], acc[i][3]);
    }
    if (dv0 == 0) {
        *(float4*)&outp[4096 + dk0]     = make_float4(nrm[0], nrm[1], nrm[2], nrm[3]);
        *(float4*)&outp[4096 + dk0 + 4] = make_float4(nrm[4], nrm[5], nrm[6], nrm[7]);
    }
}

/* ---------------- Reduce: sum SPLIT partials per head ---------------- */
__global__ void __launch_bounds__(512) reduce_k() {
    const int head = blockIdx.x;
    for (int e = threadIdx.x; e < 4160; e += 512) {
        float s = 0.f;
        #pragma unroll 8
        for (int c = 0; c < SPLIT; ++c)
            s += g_part[((size_t)head * SPLIT + c) * 4160 + e];
        if (e < 4096) g_mem[(size_t)head * 4096 + e] = s;
        else          g_norm[(size_t)head * 64 + (e - 4096)] = s;
    }
}

/* ---------------- Phase 2: retrieval GEMM + normalization (8x4 tile) ---------------- */
__global__ void __launch_bounds__(128) phase2(const float* __restrict__ q,
                                              float* __restrict__ outg) {
    /* rows padded to 68 floats to avoid bank conflicts on column-strided reads */
    __shared__ float sM[64 * 68];
    __shared__ float sQ[64 * 68];
    __shared__ float snorm[64];
    __shared__ float sdenom[64];

    const int bx   = blockIdx.x;
    const int head = bx >> 8;        /* SS/BS = 256 blocks per head */
    const int sb   = bx & 255;
    const int tid  = threadIdx.x;

    const float* mbase = g_mem + (size_t)head * 4096;
    const float* qbase = q + ((size_t)head * SS + (size_t)sb * BS) * DD;

    #pragma unroll
    for (int p = 0; p < 8; ++p) {
        int f = tid + p * 128;       /* float4 index 0..1023 */
        int r = f >> 4;
        int c = (f & 15) * 4;
        *(float4*)&sM[r * 68 + c] = *(const float4*)(mbase + (size_t)r * 64 + c);
        float4 qq = *(const float4*)(qbase + (size_t)r * 64 + c);
        qq.x = elu1(qq.x); qq.y = elu1(qq.y); qq.z = elu1(qq.z); qq.w = elu1(qq.w);
        *(float4*)&sQ[r * 68 + c] = qq;
    }
    if (tid < 64) snorm[tid] = g_norm[(size_t)head * 64 + tid];
    __syncthreads();

    /* denominator: one row per thread (tid < 64), vectorized */
    if (tid < 64) {
        float s = 0.f;
        #pragma unroll
        for (int dk = 0; dk < 64; dk += 4) {
            float4 qv = *(float4*)&sQ[tid * 68 + dk];
            float4 nv = *(float4*)&snorm[dk];
            s += qv.x * nv.x + qv.y * nv.y + qv.z * nv.z + qv.w * nv.w;
        }
        sdenom[tid] = s;
    }
    __syncthreads();

    const int s0  = (tid >> 4) * 8;  /* 0..56 */
    const int dv0 = (tid & 15) * 4;  /* 0..60 */

    float acc[8][4] = {};

    #pragma unroll 4
    for (int dk0 = 0; dk0 < 64; dk0 += 4) {
        float4 m[4];
        #pragma unroll
        for (int j = 0; j < 4; ++j)
            m[j] = *(float4*)&sM[(dk0 + j) * 68 + dv0];
        #pragma unroll
        for (int i = 0; i < 8; ++i) {
            float4 qv = *(float4*)&sQ[(s0 + i) * 68 + dk0];
            acc[i][0] += qv.x * m[0].x + qv.y * m[1].x + qv.z * m[2].x + qv.w * m[3].x;
            acc[i][1] += qv.x * m[0].y + qv.y * m[1].y + qv.z * m[2].y + qv.w * m[3].y;
            acc[i][2] += qv.x * m[0].z + qv.y * m[1].z + qv.z * m[2].z + qv.w * m[3].z;
            acc[i][3] += qv.x * m[0].w + qv.y * m[1].w + qv.z * m[2].w + qv.w * m[3].w;
        }
    }

    float* obase = outg + ((size_t)head * SS + (size_t)sb * BS) * DD;
    #pragma unroll
    for (int i = 0; i < 8; ++i) {
        float inv = 1.0f / sdenom[s0 + i];
        *(float4*)&obase[(size_t)(s0 + i) * 64 + dv0] =
            make_float4(acc[i][0] * inv, acc[i][1] * inv,
                        acc[i][2] * inv, acc[i][3] * inv);
    }
}

extern "C" void kernel_launch(void* const* d_in, const int* in_sizes, int n_in,
                              void* d_out, int out_size) {
    const float* q = (const float*)d_in[0];
    const float* k = (const float*)d_in[1];
    const float* v = (const float*)d_in[2];
    float* out = (float*)d_out;

    phase1<<<NHEADS * SPLIT, 128>>>(k, v);
    reduce_k<<<NHEADS, 512>>>();
    phase2<<<NHEADS * (SS / BS), 128>>>(q, out);
}

// round 3
// speedup vs baseline: 1.1940x; 1.0363x over previous
#include <cuda_runtime.h>

#define BB 2
#define HH 32
#define SS 16384
#define DD 64
#define NHEADS (BB*HH)
#define SPLIT 64
#define CHUNK (SS/SPLIT)   /* 256 */
#define TS 32
#define BS 64              /* s-rows per phase2 block */

/* scratch: deterministic partials + reduced memory/norm (no runtime alloc) */
__device__ float g_part[(size_t)NHEADS * SPLIT * 4160];
__device__ float g_mem [(size_t)NHEADS * 4096];
__device__ float g_norm[(size_t)NHEADS * 64];

__device__ __forceinline__ float elu1(float x) {
    return x > 0.0f ? x + 1.0f : __expf(x);
}

/* ---- packed fp32x2 primitives (FFMA2 path: 2 FMA per issue slot) ---- */
__device__ __forceinline__ void fma2(unsigned long long& d,
                                     unsigned long long a,
                                     unsigned long long b) {
    asm("fma.rn.f32x2 %0, %1, %2, %0;" : "+l"(d) : "l"(a), "l"(b));
}
__device__ __forceinline__ void add2(unsigned long long& d, unsigned long long a) {
    asm("add.rn.f32x2 %0, %0, %1;" : "+l"(d) : "l"(a));
}
__device__ __forceinline__ unsigned long long dup2(float x) {
    unsigned long long r;
    unsigned xi = __float_as_uint(x);
    asm("mov.b64 %0, {%1, %1};" : "=l"(r) : "r"(xi));
    return r;
}
__device__ __forceinline__ float2 unpk(unsigned long long v) {
    unsigned lo, hi;
    asm("mov.b64 {%0, %1}, %2;" : "=r"(lo), "=r"(hi) : "l"(v));
    return make_float2(__uint_as_float(lo), __uint_as_float(hi));
}

/* ------------- Phase 1: per-chunk partial memory + norm (FFMA2) ------------- */
__global__ void __launch_bounds__(128) phase1(const float* __restrict__ kk,
                                              const float* __restrict__ vv) {
    __shared__ float sk[TS][64];
    __shared__ float sv[TS][64];

    const int bx    = blockIdx.x;
    const int head  = bx / SPLIT;
    const int chunk = bx % SPLIT;
    const int tid   = threadIdx.x;
    const int dk0   = (tid >> 4) * 8;   /* 0..56 */
    const int dv0   = (tid & 15) * 4;   /* 0..60 */

    /* accp[ip][j]: f32x2 over dk rows (dk0+2ip, dk0+2ip+1), dv column dv0+j */
    unsigned long long accp[4][4] = {};
    unsigned long long nrmp[4]    = {};

    const float* kbase = kk + ((size_t)head * SS + (size_t)chunk * CHUNK) * DD;
    const float* vbase = vv + ((size_t)head * SS + (size_t)chunk * CHUNK) * DD;

    for (int it = 0; it < CHUNK / TS; ++it) {
        __syncthreads();
        #pragma unroll
        for (int p = 0; p < 4; ++p) {
            int f = tid + p * 128;           /* float4 index 0..511 */
            int r = f >> 4;
            int c = (f & 15) * 4;
            float4 kf = *(const float4*)(kbase + (size_t)(it * TS + r) * DD + c);
            kf.x = elu1(kf.x); kf.y = elu1(kf.y); kf.z = elu1(kf.z); kf.w = elu1(kf.w);
            *(float4*)&sk[r][c] = kf;
            *(float4*)&sv[r][c] = *(const float4*)(vbase + (size_t)(it * TS + r) * DD + c);
        }
        __syncthreads();

        #pragma unroll 4
        for (int s = 0; s < TS; ++s) {
            ulonglong2 kpa = *(ulonglong2*)&sk[s][dk0];      /* (k0,k1),(k2,k3) */
            ulonglong2 kpb = *(ulonglong2*)&sk[s][dk0 + 4];  /* (k4,k5),(k6,k7) */
            float4 vv4 = *(float4*)&sv[s][dv0];
            unsigned long long kp[4] = {kpa.x, kpa.y, kpb.x, kpb.y};
            unsigned long long vd[4];
            vd[0] = dup2(vv4.x); vd[1] = dup2(vv4.y);
            vd[2] = dup2(vv4.z); vd[3] = dup2(vv4.w);
            #pragma unroll
            for (int ip = 0; ip < 4; ++ip) {
                fma2(accp[ip][0], kp[ip], vd[0]);
                fma2(accp[ip][1], kp[ip], vd[1]);
                fma2(accp[ip][2], kp[ip], vd[2]);
                fma2(accp[ip][3], kp[ip], vd[3]);
            }
            if (dv0 == 0) {
                #pragma unroll
                for (int ip = 0; ip < 4; ++ip) add2(nrmp[ip], kp[ip]);
            }
        }
    }

    /* deterministic partial write */
    float* outp = g_part + (size_t)bx * 4160;
    #pragma unroll
    for (int ip = 0; ip < 4; ++ip) {
        float2 c0 = unpk(accp[ip][0]);
        float2 c1 = unpk(accp[ip][1]);
        float2 c2 = unpk(accp[ip][2]);
        float2 c3 = unpk(accp[ip][3]);
        *(float4*)&outp[(dk0 + 2*ip)     * 64 + dv0] = make_float4(c0.x, c1.x, c2.x, c3.x);
        *(float4*)&outp[(dk0 + 2*ip + 1) * 64 + dv0] = make_float4(c0.y, c1.y, c2.y, c3.y);
    }
    if (dv0 == 0) {
        float2 n0 = unpk(nrmp[0]), n1 = unpk(nrmp[1]);
        float2 n2 = unpk(nrmp[2]), n3 = unpk(nrmp[3]);
        *(float4*)&outp[4096 + dk0]     = make_float4(n0.x, n0.y, n1.x, n1.y);
        *(float4*)&outp[4096 + dk0 + 4] = make_float4(n2.x, n2.y, n3.x, n3.y);
    }
}

/* ---------------- Reduce: sum SPLIT partials per head ---------------- */
__global__ void __launch_bounds__(512) reduce_k() {
    const int head = blockIdx.x;
    for (int e = threadIdx.x; e < 4160; e += 512) {
        float s = 0.f;
        #pragma unroll 8
        for (int c = 0; c < SPLIT; ++c)
            s += g_part[((size_t)head * SPLIT + c) * 4160 + e];
        if (e < 4096) g_mem[(size_t)head * 4096 + e] = s;
        else          g_norm[(size_t)head * 64 + (e - 4096)] = s;
    }
}

/* ---------------- Phase 2: retrieval GEMM + normalization (FFMA2) ---------------- */
__global__ void __launch_bounds__(128) phase2(const float* __restrict__ q,
                                              float* __restrict__ outg) {
    /* rows padded to 68 floats to avoid bank conflicts on column-strided reads */
    __shared__ float sM[64 * 68];
    __shared__ float sQ[64 * 68];
    __shared__ float snorm[64];
    __shared__ float sdenom[64];

    const int bx   = blockIdx.x;
    const int head = bx >> 8;        /* SS/BS = 256 blocks per head */
    const int sb   = bx & 255;
    const int tid  = threadIdx.x;

    const float* mbase = g_mem + (size_t)head * 4096;
    const float* qbase = q + ((size_t)head * SS + (size_t)sb * BS) * DD;

    #pragma unroll
    for (int p = 0; p < 8; ++p) {
        int f = tid + p * 128;       /* float4 index 0..1023 */
        int r = f >> 4;
        int c = (f & 15) * 4;
        *(float4*)&sM[r * 68 + c] = *(const float4*)(mbase + (size_t)r * 64 + c);
        float4 qq = *(const float4*)(qbase + (size_t)r * 64 + c);
        qq.x = elu1(qq.x); qq.y = elu1(qq.y); qq.z = elu1(qq.z); qq.w = elu1(qq.w);
        *(float4*)&sQ[r * 68 + c] = qq;
    }
    if (tid < 64) snorm[tid] = g_norm[(size_t)head * 64 + tid];
    __syncthreads();

    /* denominator: one row per thread (tid < 64), vectorized */
    if (tid < 64) {
        float s = 0.f;
        #pragma unroll
        for (int dk = 0; dk < 64; dk += 4) {
            float4 qv = *(float4*)&sQ[tid * 68 + dk];
            float4 nv = *(float4*)&snorm[dk];
            s += qv.x * nv.x + qv.y * nv.y + qv.z * nv.z + qv.w * nv.w;
        }
        sdenom[tid] = s;
    }
    __syncthreads();

    const int s0  = (tid >> 4) * 8;  /* 0..56 */
    const int dv0 = (tid & 15) * 4;  /* 0..60 */

    /* accp[i][jp]: f32x2 over dv cols (dv0+2jp, dv0+2jp+1) for s-row s0+i */
    unsigned long long accp[8][2] = {};

    #pragma unroll 4
    for (int dk0 = 0; dk0 < 64; dk0 += 4) {
        unsigned long long mp[4][2];
        #pragma unroll
        for (int jj = 0; jj < 4; ++jj) {
            ulonglong2 mrow = *(ulonglong2*)&sM[(dk0 + jj) * 68 + dv0];
            mp[jj][0] = mrow.x; mp[jj][1] = mrow.y;
        }
        #pragma unroll
        for (int i = 0; i < 8; ++i) {
            float4 qv = *(float4*)&sQ[(s0 + i) * 68 + dk0];
            unsigned long long qd;
            qd = dup2(qv.x); fma2(accp[i][0], qd, mp[0][0]); fma2(accp[i][1], qd, mp[0][1]);
            qd = dup2(qv.y); fma2(accp[i][0], qd, mp[1][0]); fma2(accp[i][1], qd, mp[1][1]);
            qd = dup2(qv.z); fma2(accp[i][0], qd, mp[2][0]); fma2(accp[i][1], qd, mp[2][1]);
            qd = dup2(qv.w); fma2(accp[i][0], qd, mp[3][0]); fma2(accp[i][1], qd, mp[3][1]);
        }
    }

    float* obase = outg + ((size_t)head * SS + (size_t)sb * BS) * DD;
    #pragma unroll
    for (int i = 0; i < 8; ++i) {
        float inv = 1.0f / sdenom[s0 + i];
        float2 a = unpk(accp[i][0]);
        float2 b = unpk(accp[i][1]);
        *(float4*)&obase[(size_t)(s0 + i) * 64 + dv0] =
            make_float4(a.x * inv, a.y * inv, b.x * inv, b.y * inv);
    }
}

extern "C" void kernel_launch(void* const* d_in, const int* in_sizes, int n_in,
                              void* d_out, int out_size) {
    const float* q = (const float*)d_in[0];
    const float* k = (const float*)d_in[1];
    const float* v = (const float*)d_in[2];
    float* out = (float*)d_out;

    phase1<<<NHEADS * SPLIT, 128>>>(k, v);
    reduce_k<<<NHEADS, 512>>>();
    phase2<<<NHEADS * (SS / BS), 128>>>(q, out);
}